// round 7
// baseline (speedup 1.0000x reference)
#include <cuda_runtime.h>

#define REC      2048
#define BATCH    64
#define RSTEPS   512
#define EDIM     512
#define KTOP     819
#define GRID     128
#define NTHREADS 256
#define BK       16
#define NBAR     (1 + 2*RSTEPS)

typedef unsigned long long ull;

// ---- static device scratch ----
__device__ float g_R[BATCH * REC];
__device__ float g_part[8 * BATCH * REC];
__device__ float g_U[(size_t)RSTEPS * BATCH * REC];
__device__ unsigned g_bar;

__device__ __forceinline__ unsigned keyOf(float f) {
    unsigned b = __float_as_uint(f);
    return (b & 0x80000000u) ? ~b : (b | 0x80000000u);
}

// ---- packed f32x2: the ONLY asm is the fma itself ----
__device__ __forceinline__ ull dup32(float x) {
    unsigned u = __float_as_uint(x);
    return ((ull)u << 32) | (ull)u;
}
__device__ __forceinline__ void ffma2(ull& d, ull a, ull b) {
    asm("fma.rn.f32x2 %0, %1, %2, %0;" : "+l"(d) : "l"(a), "l"(b));
}
__device__ __forceinline__ float lo32(ull v) { return __uint_as_float((unsigned)v); }
__device__ __forceinline__ float hi32(ull v) { return __uint_as_float((unsigned)(v >> 32)); }

// ---------------------------------------------------------------------------
// GEMM tile: M=64 x N=128 x K=KLEN, 256 threads, double-buffered smem.
// Thread (tid>>3, tid&7): rows {tm2, tm2+1}, cols [tn16, tn16+16).
// 16 f32x2 accumulators (column pairs).
// NOTE: BBASE must already include the n0 column offset.
// ---------------------------------------------------------------------------
#define GEMM_BODY(ABASE, ASTRIDE, BBASE, KLEN, STORE_ROW_PTR)                  \
{                                                                              \
    const int tm2  = (tid >> 3) << 1;                                          \
    const int tn16 = (tid & 7) << 4;                                           \
    const int alm  = tid >> 2, alk4 = (tid & 3) << 2;                          \
    const int blk  = tid >> 4, bln4 = (tid & 15) << 2;                         \
    ull acc[16];                                                               \
    _Pragma("unroll")                                                          \
    for (int i = 0; i < 16; i++) acc[i] = 0ull;                                \
    float4 a4, b4a, b4b;                                                       \
    a4  = *(const float4*)&(ABASE)[(size_t)alm * (ASTRIDE) + alk4];            \
    b4a = *(const float4*)&(BBASE)[(size_t)blk * REC + bln4];                  \
    b4b = *(const float4*)&(BBASE)[(size_t)blk * REC + bln4 + 64];             \
    int buf = 0;                                                               \
    As[buf][alk4+0][alm] = a4.x; As[buf][alk4+1][alm] = a4.y;                  \
    As[buf][alk4+2][alm] = a4.z; As[buf][alk4+3][alm] = a4.w;                  \
    *(float4*)&Ws[buf][blk][bln4]      = b4a;                                  \
    *(float4*)&Ws[buf][blk][bln4 + 64] = b4b;                                  \
    __syncthreads();                                                           \
    _Pragma("unroll 1")                                                        \
    for (int it = 0; it < (KLEN) / BK; it++) {                                 \
        const int k1 = (it + 1) * BK;                                          \
        const bool more = (k1 < (KLEN));                                       \
        if (more) {                                                            \
            a4  = *(const float4*)&(ABASE)[(size_t)alm * (ASTRIDE) + k1 + alk4];\
            b4a = *(const float4*)&(BBASE)[(size_t)(k1 + blk) * REC + bln4];   \
            b4b = *(const float4*)&(BBASE)[(size_t)(k1 + blk) * REC + bln4 + 64];\
        }                                                                      \
        _Pragma("unroll")                                                      \
        for (int kk = 0; kk < BK; kk++) {                                      \
            float2 a2 = *(const float2*)&As[buf][kk][tm2];                     \
            ull ad0 = dup32(a2.x);                                             \
            ull ad1 = dup32(a2.y);                                             \
            const ulonglong2* wp = (const ulonglong2*)&Ws[buf][kk][tn16];      \
            ulonglong2 p0 = wp[0];                                             \
            ulonglong2 p1 = wp[1];                                             \
            ulonglong2 p2 = wp[2];                                             \
            ulonglong2 p3 = wp[3];                                             \
            ffma2(acc[0],  ad0, p0.x); ffma2(acc[1],  ad0, p0.y);              \
            ffma2(acc[2],  ad0, p1.x); ffma2(acc[3],  ad0, p1.y);              \
            ffma2(acc[4],  ad0, p2.x); ffma2(acc[5],  ad0, p2.y);              \
            ffma2(acc[6],  ad0, p3.x); ffma2(acc[7],  ad0, p3.y);              \
            ffma2(acc[8],  ad1, p0.x); ffma2(acc[9],  ad1, p0.y);              \
            ffma2(acc[10], ad1, p1.x); ffma2(acc[11], ad1, p1.y);              \
            ffma2(acc[12], ad1, p2.x); ffma2(acc[13], ad1, p2.y);              \
            ffma2(acc[14], ad1, p3.x); ffma2(acc[15], ad1, p3.y);              \
        }                                                                      \
        if (more) {                                                            \
            As[buf^1][alk4+0][alm] = a4.x; As[buf^1][alk4+1][alm] = a4.y;      \
            As[buf^1][alk4+2][alm] = a4.z; As[buf^1][alk4+3][alm] = a4.w;      \
            *(float4*)&Ws[buf^1][blk][bln4]      = b4a;                        \
            *(float4*)&Ws[buf^1][blk][bln4 + 64] = b4b;                        \
        }                                                                      \
        __syncthreads();                                                       \
        buf ^= 1;                                                              \
    }                                                                          \
    _Pragma("unroll")                                                          \
    for (int i = 0; i < 2; i++) {                                              \
        int row = tm2 + i;                                                     \
        float* op = STORE_ROW_PTR;                                             \
        _Pragma("unroll")                                                      \
        for (int p = 0; p < 4; p++) {                                          \
            ull e0 = acc[i*8 + 2*p];                                           \
            ull e1 = acc[i*8 + 2*p + 1];                                       \
            *(float4*)&op[tn16 + 4*p] =                                        \
                make_float4(lo32(e0), hi32(e0), lo32(e1), hi32(e1));           \
        }                                                                      \
    }                                                                          \
}

// ---------------------------------------------------------------------------
// Precompute U[t][b][:] = x[b,t,:] @ W_input.  grid (16, 512), 256 threads.
// FIX (R7): B base must include the n0 column offset -> (Wi + n0).
// ---------------------------------------------------------------------------
__global__ void __launch_bounds__(NTHREADS) precompute_u_kernel(
    const float* __restrict__ x, const float* __restrict__ Wi)
{
    __shared__ float As[2][BK][68];
    __shared__ float Ws[2][BK][128];
    const int t   = blockIdx.y;
    const int n0  = blockIdx.x * 128;
    const int tid = threadIdx.x;
    const float* Ab = x + (size_t)t * EDIM;
    const float* Bb = Wi + n0;
    GEMM_BODY(Ab, RSTEPS * EDIM, Bb, EDIM,
              (&g_U[((size_t)t * BATCH + row) * REC + n0]))
}

// ---------------------------------------------------------------------------
__device__ __forceinline__ void grid_barrier(unsigned target) {
    __syncthreads();
    if (threadIdx.x == 0) {
        __threadfence();
        atomicAdd(&g_bar, 1u);
        while (*(volatile unsigned*)&g_bar < target) { __nanosleep(32); }
        __threadfence();
    }
    __syncthreads();
}

__global__ void __launch_bounds__(NTHREADS) persist_kernel(
    const float* __restrict__ Wr, float* __restrict__ out)
{
    __shared__ float As[2][BK][68];
    __shared__ float Ws[2][BK][128];
    __shared__ float zrow[REC];
    __shared__ float urow[REC];
    __shared__ unsigned hist[256];
    __shared__ unsigned sh_prefix, sh_k;
    __shared__ float red[8];

    const int bid = blockIdx.x;
    const int tid = threadIdx.x;

    for (int i = bid * NTHREADS + tid; i < BATCH * REC; i += GRID * NTHREADS)
        g_R[i] = 0.0f;
    unsigned baridx = 1;
    grid_barrier(baridx * GRID);

    const int ntile = bid & 15;
    const int kc    = bid >> 4;
    const int n0    = ntile * 128;
    const int kbase = kc * 256;
    const int m     = bid;
    const float* Ab = g_R + kbase;
    const float* Bb = Wr + (size_t)kbase * REC + n0;

    for (int step = 0; step < RSTEPS; step++) {
        // -------- phase A: K-split GEMM tile --------
        GEMM_BODY(Ab, REC, Bb, 256,
                  (&g_part[((size_t)kc * BATCH + row) * REC + n0]))
        baridx++;
        grid_barrier(baridx * GRID);

        // -------- phase B: reduce + exact top-k threshold + tanh + norm ----
        if (bid < BATCH) {
            for (int j = tid; j < REC; j += NTHREADS) {
                float zz = 0.0f;
                #pragma unroll
                for (int c = 0; c < 8; c++)
                    zz += g_part[((size_t)c * BATCH + m) * REC + j];
                zrow[j] = zz;
                urow[j] = g_U[((size_t)step * BATCH + m) * REC + j];
            }
            if (tid == 0) { sh_prefix = 0u; sh_k = KTOP; }
            __syncthreads();

            // radix select (R4-proven serial scan)
            #pragma unroll
            for (int shift = 24; shift >= 0; shift -= 8) {
                hist[tid] = 0u;
                __syncthreads();
                unsigned prefix = sh_prefix;
                unsigned maskH  = (shift == 24) ? 0u : (0xFFFFFFFFu << (shift + 8));
                for (int j = tid; j < REC; j += NTHREADS) {
                    unsigned key = keyOf(zrow[j]);
                    if (((key ^ prefix) & maskH) == 0u)
                        atomicAdd(&hist[(key >> shift) & 0xFFu], 1u);
                }
                __syncthreads();
                if (tid == 0) {
                    unsigned k = sh_k, cum = 0u;
                    int b2 = 255;
                    for (; b2 >= 0; b2--) { cum += hist[b2]; if (cum >= k) break; }
                    sh_k = k - (cum - hist[b2]);
                    sh_prefix = prefix | ((unsigned)b2 << shift);
                }
                __syncthreads();
            }
            const unsigned thKey = sh_prefix;

            float part = 0.0f;
            #pragma unroll
            for (int jj = 0; jj < REC / NTHREADS; jj++) {
                int j = tid + jj * NTHREADS;
                float zz = zrow[j];
                float s  = (keyOf(zz) >= thKey) ? zz : 0.0f;
                float v  = tanhf(urow[j] + s);
                zrow[j]  = v;
                part += v * v;
            }
            #pragma unroll
            for (int o = 16; o > 0; o >>= 1)
                part += __shfl_down_sync(0xFFFFFFFFu, part, o);
            if ((tid & 31) == 0) red[tid >> 5] = part;
            __syncthreads();
            if (tid < 32) {
                float v = (tid < 8) ? red[tid] : 0.0f;
                #pragma unroll
                for (int o = 4; o > 0; o >>= 1)
                    v += __shfl_down_sync(0xFFFFFFFFu, v, o);
                if (tid == 0) red[0] = v;
            }
            __syncthreads();
            const float inv = 1.0f / (sqrtf(red[0]) + 1e-6f);
            #pragma unroll
            for (int jj = 0; jj < REC / NTHREADS; jj++) {
                int j = tid + jj * NTHREADS;
                float v = zrow[j] * inv;
                g_R[(size_t)m * REC + j] = v;
                if (step == RSTEPS - 1) out[(size_t)m * REC + j] = v;
            }
        }
        baridx++;
        if (step < RSTEPS - 1) {
            grid_barrier(baridx * GRID);
        } else {
            __syncthreads();
            if (tid == 0) {
                __threadfence();
                unsigned p = atomicAdd(&g_bar, 1u);
                if (p == (unsigned)NBAR * GRID - 1u) atomicExch(&g_bar, 0u);
            }
        }
    }
}

// ---------------------------------------------------------------------------
extern "C" void kernel_launch(void* const* d_in, const int* in_sizes, int n_in,
                              void* d_out, int out_size)
{
    const float* x  = nullptr;   // 64*512*512  = 16777216
    const float* Wi = nullptr;   // 512*2048    = 1048576
    const float* Wr = nullptr;   // 2048*2048   = 4194304
    for (int i = 0; i < n_in; i++) {
        if      (in_sizes[i] == BATCH * RSTEPS * EDIM) x  = (const float*)d_in[i];
        else if (in_sizes[i] == EDIM * REC)            Wi = (const float*)d_in[i];
        else if (in_sizes[i] == REC * REC)             Wr = (const float*)d_in[i];
    }
    float* out = (float*)d_out;

    precompute_u_kernel<<<dim3(REC / 128, RSTEPS), NTHREADS>>>(x, Wi);
    persist_kernel<<<GRID, NTHREADS>>>(Wr, out);
}

// round 8
// speedup vs baseline: 3.1535x; 3.1535x over previous
#include <cuda_runtime.h>
#include <cuda_bf16.h>

#define REC      2048
#define BATCH    64
#define RSTEPS   512
#define EDIM     512
#define KTOP     819
#define GRID     128
#define PTHREADS 256          // persist kernel threads (8 warps)
#define BK       16
#define NBAR     (1 + 2*RSTEPS)

typedef unsigned long long ull;

// ---- static device scratch ----
__device__ __nv_bfloat16 g_Rh[BATCH * REC];              // r hi (bf16)
__device__ __nv_bfloat16 g_Rl[BATCH * REC];              // r lo (bf16)
__device__ __nv_bfloat16 g_WhT[(size_t)REC * REC];       // Wr hi, TRANSPOSED [n][k]
__device__ __nv_bfloat16 g_WlT[(size_t)REC * REC];       // Wr lo, TRANSPOSED [n][k]
__device__ float g_part[8 * BATCH * REC];                // K-split partials
__device__ float g_U[(size_t)RSTEPS * BATCH * REC];      // precomputed x @ W_in
__device__ unsigned g_bar;

__device__ __forceinline__ unsigned keyOf(float f) {
    unsigned b = __float_as_uint(f);
    return (b & 0x80000000u) ? ~b : (b | 0x80000000u);
}

// ---- tensor-core primitives ----
__device__ __forceinline__ void ldsm4v(unsigned* r, unsigned addr) {
    asm volatile("ldmatrix.sync.aligned.m8n8.x4.shared.b16 {%0,%1,%2,%3}, [%4];"
                 : "=r"(r[0]), "=r"(r[1]), "=r"(r[2]), "=r"(r[3]) : "r"(addr));
}
__device__ __forceinline__ void mma16816(float* d, const unsigned* a,
                                         unsigned b0, unsigned b1) {
    asm volatile("mma.sync.aligned.m16n8k16.row.col.f32.bf16.bf16.f32 "
                 "{%0,%1,%2,%3}, {%4,%5,%6,%7}, {%8,%9}, {%0,%1,%2,%3};"
                 : "+f"(d[0]), "+f"(d[1]), "+f"(d[2]), "+f"(d[3])
                 : "r"(a[0]), "r"(a[1]), "r"(a[2]), "r"(a[3]), "r"(b0), "r"(b1));
}

// ---------------------------------------------------------------------------
// One-time: split Wr (fp32, [k][n]) into bf16 hi/lo, transposed to [n][k].
// grid (32, 32) of 64x64 tiles, 256 threads.
// ---------------------------------------------------------------------------
__global__ void __launch_bounds__(256) split_w_kernel(const float* __restrict__ Wr)
{
    __shared__ float tile[64][65];
    const int k0 = blockIdx.y * 64, n0 = blockIdx.x * 64;
    const int tid = threadIdx.x;
    #pragma unroll
    for (int i = 0; i < 16; i++) {
        int idx = tid + (i << 8);
        int r = idx >> 6, c = idx & 63;
        tile[r][c] = Wr[(size_t)(k0 + r) * REC + n0 + c];
    }
    __syncthreads();
    #pragma unroll
    for (int i = 0; i < 16; i++) {
        int idx = tid + (i << 8);
        int nn = idx >> 6, kk = idx & 63;
        float w = tile[kk][nn];
        __nv_bfloat16 h = __float2bfloat16(w);
        float lo = w - __bfloat162float(h);
        g_WhT[(size_t)(n0 + nn) * REC + (k0 + kk)] = h;
        g_WlT[(size_t)(n0 + nn) * REC + (k0 + kk)] = __float2bfloat16(lo);
    }
}

// ---------------------------------------------------------------------------
// Precompute U[t][b][:] = x[b,t,:] @ W_input.  (R4-proven scalar kernel.)
// ---------------------------------------------------------------------------
__global__ void __launch_bounds__(512) precompute_u_kernel(
    const float* __restrict__ x, const float* __restrict__ Wi)
{
    __shared__ float As[2][BK][68];
    __shared__ float Ws[2][BK][128];

    const int t   = blockIdx.y;
    const int n0  = blockIdx.x * 128;
    const int tid = threadIdx.x;
    const int tm  = tid >> 5, tn = tid & 31;
    const int alm = tid >> 2, alk4 = (tid & 3) << 2;
    const int blk = tid >> 5, bln4 = (tid & 31) << 2;

    float acc[4][4];
    #pragma unroll
    for (int i = 0; i < 4; i++)
        #pragma unroll
        for (int j = 0; j < 4; j++) acc[i][j] = 0.0f;

    float4 a4, b4;
    if (tid < 256)
        a4 = *(const float4*)&x[((size_t)alm * RSTEPS + t) * EDIM + alk4];
    b4 = *(const float4*)&Wi[(size_t)blk * REC + n0 + bln4];

    int buf = 0;
    if (tid < 256) {
        As[buf][alk4+0][alm] = a4.x; As[buf][alk4+1][alm] = a4.y;
        As[buf][alk4+2][alm] = a4.z; As[buf][alk4+3][alm] = a4.w;
    }
    *(float4*)&Ws[buf][blk][bln4] = b4;
    __syncthreads();

    #pragma unroll 1
    for (int it = 0; it < EDIM / BK; it++) {
        const int k1 = (it + 1) * BK;
        const bool more = (k1 < EDIM);
        if (more) {
            if (tid < 256)
                a4 = *(const float4*)&x[((size_t)alm * RSTEPS + t) * EDIM + k1 + alk4];
            b4 = *(const float4*)&Wi[(size_t)(k1 + blk) * REC + n0 + bln4];
        }
        #pragma unroll
        for (int kk = 0; kk < BK; kk++) {
            float4 a = *(const float4*)&As[buf][kk][tm << 2];
            float4 b = *(const float4*)&Ws[buf][kk][tn << 2];
            float av[4] = {a.x, a.y, a.z, a.w};
            float bv[4] = {b.x, b.y, b.z, b.w};
            #pragma unroll
            for (int i = 0; i < 4; i++)
                #pragma unroll
                for (int j = 0; j < 4; j++)
                    acc[i][j] = fmaf(av[i], bv[j], acc[i][j]);
        }
        if (more) {
            if (tid < 256) {
                As[buf^1][alk4+0][alm] = a4.x; As[buf^1][alk4+1][alm] = a4.y;
                As[buf^1][alk4+2][alm] = a4.z; As[buf^1][alk4+3][alm] = a4.w;
            }
            *(float4*)&Ws[buf^1][blk][bln4] = b4;
        }
        __syncthreads();
        buf ^= 1;
    }

    #pragma unroll
    for (int i = 0; i < 4; i++) {
        int b = (tm << 2) + i;
        *(float4*)&g_U[((size_t)t * BATCH + b) * REC + n0 + (tn << 2)] =
            make_float4(acc[i][0], acc[i][1], acc[i][2], acc[i][3]);
    }
}

// ---------------------------------------------------------------------------
__device__ __forceinline__ void grid_barrier(unsigned target) {
    __syncthreads();
    if (threadIdx.x == 0) {
        __threadfence();
        atomicAdd(&g_bar, 1u);
        while (*(volatile unsigned*)&g_bar < target) { __nanosleep(32); }
        __threadfence();
    }
    __syncthreads();
}

// ---------------------------------------------------------------------------
// Persistent scan. Phase A: per block one 64(M) x 128(N) x 256(K) tile of
// z = rh@Wh + rl@Wh + rh@Wl  (bf16 mma.sync, fp32 accum), K sub-chunks of 64.
// Phase B: blocks 0..63 = per-row reduce + exact radix top-k + tanh + norm.
// ---------------------------------------------------------------------------
__global__ void __launch_bounds__(PTHREADS) persist_kernel(float* __restrict__ out)
{
    // GEMM tiles (phase A) and zrow/urow (phase B) alias the same storage;
    // the grid barrier separates their lifetimes.
    __shared__ __align__(16) unsigned char smem_raw[36864];
    __shared__ unsigned hist[256];
    __shared__ unsigned sh_prefix, sh_k;
    __shared__ float red[8];

    __nv_bfloat16 (*As_h)[72] = (__nv_bfloat16(*)[72])(smem_raw);
    __nv_bfloat16 (*As_l)[72] = (__nv_bfloat16(*)[72])(smem_raw + 9216);
    __nv_bfloat16 (*Bs)[72]   = (__nv_bfloat16(*)[72])(smem_raw + 18432);
    float* zrow = (float*)smem_raw;             // 2048 floats
    float* urow = (float*)(smem_raw + 8192);    // 2048 floats

    const int bid = blockIdx.x;
    const int tid = threadIdx.x;
    const int lane = tid & 31;
    const int wid  = tid >> 5;

    // zero recurrent state (bf16 zero == 0x0000)
    for (int i = bid * PTHREADS + tid; i < BATCH * REC; i += GRID * PTHREADS) {
        g_Rh[i] = __float2bfloat16(0.0f);
        g_Rl[i] = __float2bfloat16(0.0f);
    }
    unsigned baridx = 1;
    grid_barrier(baridx * GRID);

    const int ntile = bid & 15;
    const int kc    = bid >> 4;
    const int n0    = ntile * 128;
    const int kbase = kc * 256;
    const int m     = bid;

    // warp tile: 4 warps along M (16 each), 2 along N (64 each)
    const int m0w = (wid & 3) << 4;
    const int n0w = (wid >> 2) << 6;
    const unsigned sAh = (unsigned)__cvta_generic_to_shared(&As_h[0][0]);
    const unsigned sAl = (unsigned)__cvta_generic_to_shared(&As_l[0][0]);
    const unsigned sB  = (unsigned)__cvta_generic_to_shared(&Bs[0][0]);
    // per-lane ldmatrix row/col offset (elements): row = (lane&15), col8 = (lane>>4)*8
    const unsigned lrow = (lane & 15);
    const unsigned lcol = (lane >> 4) << 3;

    for (int step = 0; step < RSTEPS; step++) {
        // ================= phase A =================
        {
            float acc[8][4];
            #pragma unroll
            for (int f = 0; f < 8; f++)
                #pragma unroll
                for (int q = 0; q < 4; q++) acc[f][q] = 0.0f;

            #pragma unroll 1
            for (int s = 0; s < 4; s++) {
                const int ksub = kbase + (s << 6);
                __syncthreads();
                // load A hi/lo tiles (64x64 bf16 each)
                #pragma unroll
                for (int i = 0; i < 2; i++) {
                    int c = tid + (i << 8);
                    int row = c >> 3, col = (c & 7) << 3;
                    *(uint4*)&As_h[row][col] =
                        *(const uint4*)&g_Rh[row * REC + ksub + col];
                    *(uint4*)&As_l[row][col] =
                        *(const uint4*)&g_Rl[row * REC + ksub + col];
                }
                // load B hi tile (128x64 bf16)
                #pragma unroll
                for (int i = 0; i < 4; i++) {
                    int c = tid + (i << 8);
                    int row = c >> 3, col = (c & 7) << 3;
                    *(uint4*)&Bs[row][col] =
                        *(const uint4*)&g_WhT[(size_t)(n0 + row) * REC + ksub + col];
                }
                __syncthreads();

                // A fragments for all 4 k16-steps (hi and lo)
                unsigned Ah[4][4], Al[4][4];
                #pragma unroll
                for (int kst = 0; kst < 4; kst++) {
                    unsigned off = ((m0w + lrow) * 72 + (kst << 4) + lcol) << 1;
                    ldsm4v(Ah[kst], sAh + off);
                    ldsm4v(Al[kst], sAl + off);
                }
                // pass 1+2: (rh + rl) @ Wh
                #pragma unroll
                for (int kst = 0; kst < 4; kst++) {
                    #pragma unroll
                    for (int ng = 0; ng < 4; ng++) {
                        unsigned r[4];
                        unsigned off = ((n0w + (ng << 4) + lrow) * 72 + (kst << 4) + lcol) << 1;
                        ldsm4v(r, sB + off);
                        mma16816(acc[2*ng],   Ah[kst], r[0], r[2]);
                        mma16816(acc[2*ng+1], Ah[kst], r[1], r[3]);
                        mma16816(acc[2*ng],   Al[kst], r[0], r[2]);
                        mma16816(acc[2*ng+1], Al[kst], r[1], r[3]);
                    }
                }
                __syncthreads();
                // load B lo tile
                #pragma unroll
                for (int i = 0; i < 4; i++) {
                    int c = tid + (i << 8);
                    int row = c >> 3, col = (c & 7) << 3;
                    *(uint4*)&Bs[row][col] =
                        *(const uint4*)&g_WlT[(size_t)(n0 + row) * REC + ksub + col];
                }
                __syncthreads();
                // pass 3: rh @ Wl
                #pragma unroll
                for (int kst = 0; kst < 4; kst++) {
                    #pragma unroll
                    for (int ng = 0; ng < 4; ng++) {
                        unsigned r[4];
                        unsigned off = ((n0w + (ng << 4) + lrow) * 72 + (kst << 4) + lcol) << 1;
                        ldsm4v(r, sB + off);
                        mma16816(acc[2*ng],   Ah[kst], r[0], r[2]);
                        mma16816(acc[2*ng+1], Ah[kst], r[1], r[3]);
                    }
                }
            }

            // epilogue: scatter accumulators to g_part
            const int g  = lane >> 2;
            const int tg = lane & 3;
            #pragma unroll
            for (int f = 0; f < 8; f++) {
                int col  = n0 + n0w + (f << 3) + (tg << 1);
                int row0 = m0w + g;
                *(float2*)&g_part[((size_t)kc * BATCH + row0) * REC + col] =
                    make_float2(acc[f][0], acc[f][1]);
                *(float2*)&g_part[((size_t)kc * BATCH + row0 + 8) * REC + col] =
                    make_float2(acc[f][2], acc[f][3]);
            }
        }
        baridx++;
        grid_barrier(baridx * GRID);

        // ================= phase B =================
        if (bid < BATCH) {
            for (int j = tid; j < REC; j += PTHREADS) {
                float zz = 0.0f;
                #pragma unroll
                for (int c = 0; c < 8; c++)
                    zz += g_part[((size_t)c * BATCH + m) * REC + j];
                zrow[j] = zz;
                urow[j] = g_U[((size_t)step * BATCH + m) * REC + j];
            }
            if (tid == 0) { sh_prefix = 0u; sh_k = KTOP; }
            __syncthreads();

            // exact radix select (R4-proven serial scan)
            #pragma unroll
            for (int shift = 24; shift >= 0; shift -= 8) {
                hist[tid] = 0u;
                __syncthreads();
                unsigned prefix = sh_prefix;
                unsigned maskH  = (shift == 24) ? 0u : (0xFFFFFFFFu << (shift + 8));
                for (int j = tid; j < REC; j += PTHREADS) {
                    unsigned key = keyOf(zrow[j]);
                    if (((key ^ prefix) & maskH) == 0u)
                        atomicAdd(&hist[(key >> shift) & 0xFFu], 1u);
                }
                __syncthreads();
                if (tid == 0) {
                    unsigned k = sh_k, cum = 0u;
                    int b2 = 255;
                    for (; b2 >= 0; b2--) { cum += hist[b2]; if (cum >= k) break; }
                    sh_k = k - (cum - hist[b2]);
                    sh_prefix = prefix | ((unsigned)b2 << shift);
                }
                __syncthreads();
            }
            const unsigned thKey = sh_prefix;

            float part = 0.0f;
            #pragma unroll
            for (int jj = 0; jj < REC / PTHREADS; jj++) {
                int j = tid + jj * PTHREADS;
                float zz = zrow[j];
                float sv = (keyOf(zz) >= thKey) ? zz : 0.0f;
                float v  = tanhf(urow[j] + sv);
                zrow[j]  = v;
                part += v * v;
            }
            #pragma unroll
            for (int o = 16; o > 0; o >>= 1)
                part += __shfl_down_sync(0xFFFFFFFFu, part, o);
            if ((tid & 31) == 0) red[tid >> 5] = part;
            __syncthreads();
            if (tid < 32) {
                float v = (tid < 8) ? red[tid] : 0.0f;
                #pragma unroll
                for (int o = 4; o > 0; o >>= 1)
                    v += __shfl_down_sync(0xFFFFFFFFu, v, o);
                if (tid == 0) red[0] = v;
            }
            __syncthreads();
            const float inv = 1.0f / (sqrtf(red[0]) + 1e-6f);
            #pragma unroll
            for (int jj = 0; jj < REC / PTHREADS; jj++) {
                int j = tid + jj * PTHREADS;
                float v = zrow[j] * inv;
                __nv_bfloat16 h = __float2bfloat16(v);
                g_Rh[(size_t)m * REC + j] = h;
                g_Rl[(size_t)m * REC + j] =
                    __float2bfloat16(v - __bfloat162float(h));
                if (step == RSTEPS - 1) out[(size_t)m * REC + j] = v;
            }
        }
        baridx++;
        if (step < RSTEPS - 1) {
            grid_barrier(baridx * GRID);
        } else {
            __syncthreads();
            if (tid == 0) {
                __threadfence();
                unsigned p = atomicAdd(&g_bar, 1u);
                if (p == (unsigned)NBAR * GRID - 1u) atomicExch(&g_bar, 0u);
            }
        }
    }
}

// ---------------------------------------------------------------------------
extern "C" void kernel_launch(void* const* d_in, const int* in_sizes, int n_in,
                              void* d_out, int out_size)
{
    const float* x  = nullptr;   // 64*512*512  = 16777216
    const float* Wi = nullptr;   // 512*2048    = 1048576
    const float* Wr = nullptr;   // 2048*2048   = 4194304
    for (int i = 0; i < n_in; i++) {
        if      (in_sizes[i] == BATCH * RSTEPS * EDIM) x  = (const float*)d_in[i];
        else if (in_sizes[i] == EDIM * REC)            Wi = (const float*)d_in[i];
        else if (in_sizes[i] == REC * REC)             Wr = (const float*)d_in[i];
    }
    float* out = (float*)d_out;

    split_w_kernel<<<dim3(32, 32), 256>>>(Wr);
    precompute_u_kernel<<<dim3(REC / 128, RSTEPS), 512>>>(x, Wi);
    persist_kernel<<<GRID, PTHREADS>>>(out);
}

// round 9
// speedup vs baseline: 6.2900x; 1.9946x over previous
#include <cuda_runtime.h>
#include <cuda_bf16.h>

#define REC      2048
#define BATCH    64
#define RSTEPS   512
#define EDIM     512
#define KTOP     819
#define GRID     128
#define PTHREADS 256
#define NBAR     (1 + 2*RSTEPS)

// ---- static device scratch ----
__device__ __nv_bfloat16 g_Rh[BATCH * REC];
__device__ __nv_bfloat16 g_Rl[BATCH * REC];
__device__ __nv_bfloat16 g_WhT[(size_t)REC * REC];        // Wr hi, [n][k]
__device__ __nv_bfloat16 g_WlT[(size_t)REC * REC];        // Wr lo, [n][k]
__device__ __nv_bfloat16 g_WiTh[(size_t)REC * EDIM];      // Wi hi, [n][k]
__device__ __nv_bfloat16 g_WiTl[(size_t)REC * EDIM];      // Wi lo, [n][k]
__device__ __nv_bfloat16 g_Xh[(size_t)BATCH * RSTEPS * EDIM];
__device__ __nv_bfloat16 g_Xl[(size_t)BATCH * RSTEPS * EDIM];
__device__ float g_part[8 * BATCH * REC];
__device__ float g_U[(size_t)RSTEPS * BATCH * REC];
__device__ unsigned g_bar;

__device__ __forceinline__ unsigned keyOf(float f) {
    unsigned b = __float_as_uint(f);
    return (b & 0x80000000u) ? ~b : (b | 0x80000000u);
}

// ---- tensor-core primitives (R8-proven) ----
__device__ __forceinline__ void ldsm4v(unsigned* r, unsigned addr) {
    asm volatile("ldmatrix.sync.aligned.m8n8.x4.shared.b16 {%0,%1,%2,%3}, [%4];"
                 : "=r"(r[0]), "=r"(r[1]), "=r"(r[2]), "=r"(r[3]) : "r"(addr));
}
__device__ __forceinline__ void mma16816(float* d, const unsigned* a,
                                         unsigned b0, unsigned b1) {
    asm volatile("mma.sync.aligned.m16n8k16.row.col.f32.bf16.bf16.f32 "
                 "{%0,%1,%2,%3}, {%4,%5,%6,%7}, {%8,%9}, {%0,%1,%2,%3};"
                 : "+f"(d[0]), "+f"(d[1]), "+f"(d[2]), "+f"(d[3])
                 : "r"(a[0]), "r"(a[1]), "r"(a[2]), "r"(a[3]), "r"(b0), "r"(b1));
}

// ---------------------------------------------------------------------------
// Shared 64(M) x 128(N) x (nsub*64)(K) tile: out = Ah@Bh + Al@Bh + Ah@Bl.
// Byte-for-byte the R8-proven phase-A body, parameterized by pointers/strides.
// Caller pre-applies row/col base offsets to Ah/Al/Bh/Bl/outBase.
// ---------------------------------------------------------------------------
__device__ __forceinline__ void mma_tile_64x128(
    const __nv_bfloat16* __restrict__ Ah, const __nv_bfloat16* __restrict__ Al,
    size_t strideA,
    const __nv_bfloat16* __restrict__ Bh, const __nv_bfloat16* __restrict__ Bl,
    size_t strideB,
    int nsub,
    float* __restrict__ outBase, size_t strideO,
    __nv_bfloat16 (*As_h)[72], __nv_bfloat16 (*As_l)[72], __nv_bfloat16 (*Bs)[72],
    int tid)
{
    const int lane = tid & 31, wid = tid >> 5;
    const int m0w = (wid & 3) << 4;
    const int n0w = (wid >> 2) << 6;
    const unsigned sAh = (unsigned)__cvta_generic_to_shared(&As_h[0][0]);
    const unsigned sAl = (unsigned)__cvta_generic_to_shared(&As_l[0][0]);
    const unsigned sB  = (unsigned)__cvta_generic_to_shared(&Bs[0][0]);
    const unsigned lrow = (lane & 15);
    const unsigned lcol = (lane >> 4) << 3;

    float acc[8][4];
    #pragma unroll
    for (int f = 0; f < 8; f++)
        #pragma unroll
        for (int q = 0; q < 4; q++) acc[f][q] = 0.0f;

    #pragma unroll 1
    for (int s = 0; s < nsub; s++) {
        const int ksub = s << 6;
        __syncthreads();
        #pragma unroll
        for (int i = 0; i < 2; i++) {
            int c = tid + (i << 8);
            int row = c >> 3, col = (c & 7) << 3;
            *(uint4*)&As_h[row][col] = *(const uint4*)&Ah[(size_t)row * strideA + ksub + col];
            *(uint4*)&As_l[row][col] = *(const uint4*)&Al[(size_t)row * strideA + ksub + col];
        }
        #pragma unroll
        for (int i = 0; i < 4; i++) {
            int c = tid + (i << 8);
            int row = c >> 3, col = (c & 7) << 3;
            *(uint4*)&Bs[row][col] = *(const uint4*)&Bh[(size_t)row * strideB + ksub + col];
        }
        __syncthreads();

        unsigned Afh[4][4], Afl[4][4];
        #pragma unroll
        for (int kst = 0; kst < 4; kst++) {
            unsigned off = ((m0w + lrow) * 72 + (kst << 4) + lcol) << 1;
            ldsm4v(Afh[kst], sAh + off);
            ldsm4v(Afl[kst], sAl + off);
        }
        #pragma unroll
        for (int kst = 0; kst < 4; kst++) {
            #pragma unroll
            for (int ng = 0; ng < 4; ng++) {
                unsigned r[4];
                unsigned off = ((n0w + (ng << 4) + lrow) * 72 + (kst << 4) + lcol) << 1;
                ldsm4v(r, sB + off);
                mma16816(acc[2*ng],   Afh[kst], r[0], r[2]);
                mma16816(acc[2*ng+1], Afh[kst], r[1], r[3]);
                mma16816(acc[2*ng],   Afl[kst], r[0], r[2]);
                mma16816(acc[2*ng+1], Afl[kst], r[1], r[3]);
            }
        }
        __syncthreads();
        #pragma unroll
        for (int i = 0; i < 4; i++) {
            int c = tid + (i << 8);
            int row = c >> 3, col = (c & 7) << 3;
            *(uint4*)&Bs[row][col] = *(const uint4*)&Bl[(size_t)row * strideB + ksub + col];
        }
        __syncthreads();
        #pragma unroll
        for (int kst = 0; kst < 4; kst++) {
            #pragma unroll
            for (int ng = 0; ng < 4; ng++) {
                unsigned r[4];
                unsigned off = ((n0w + (ng << 4) + lrow) * 72 + (kst << 4) + lcol) << 1;
                ldsm4v(r, sB + off);
                mma16816(acc[2*ng],   Afh[kst], r[0], r[2]);
                mma16816(acc[2*ng+1], Afh[kst], r[1], r[3]);
            }
        }
    }

    const int g  = lane >> 2;
    const int tg = lane & 3;
    #pragma unroll
    for (int f = 0; f < 8; f++) {
        int coloff = n0w + (f << 3) + (tg << 1);
        int row0   = m0w + g;
        *(float2*)&outBase[(size_t)row0 * strideO + coloff] =
            make_float2(acc[f][0], acc[f][1]);
        *(float2*)&outBase[(size_t)(row0 + 8) * strideO + coloff] =
            make_float2(acc[f][2], acc[f][3]);
    }
}

// ---------------------------------------------------------------------------
// One-time splits.
// mode 0: Wr [REC][REC] -> g_WhT/g_WlT ; mode 1: Wi [EDIM][REC] -> g_WiTh/g_WiTl
// ---------------------------------------------------------------------------
__global__ void __launch_bounds__(256) split_transpose_kernel(
    const float* __restrict__ W, int Kdim, int Ndim, int mode)
{
    __shared__ float tile[64][65];
    __nv_bfloat16* outH = mode ? g_WiTh : g_WhT;
    __nv_bfloat16* outL = mode ? g_WiTl : g_WlT;
    const int k0 = blockIdx.y * 64, n0 = blockIdx.x * 64;
    const int tid = threadIdx.x;
    #pragma unroll
    for (int i = 0; i < 16; i++) {
        int idx = tid + (i << 8);
        int r = idx >> 6, c = idx & 63;
        tile[r][c] = W[(size_t)(k0 + r) * Ndim + n0 + c];
    }
    __syncthreads();
    #pragma unroll
    for (int i = 0; i < 16; i++) {
        int idx = tid + (i << 8);
        int nn = idx >> 6, kk = idx & 63;
        float w = tile[kk][nn];
        __nv_bfloat16 h = __float2bfloat16(w);
        outH[(size_t)(n0 + nn) * Kdim + (k0 + kk)] = h;
        outL[(size_t)(n0 + nn) * Kdim + (k0 + kk)] =
            __float2bfloat16(w - __bfloat162float(h));
    }
}

__global__ void __launch_bounds__(256) split_x_kernel(const float* __restrict__ x)
{
    size_t i = (size_t)blockIdx.x * 256 + threadIdx.x;
    float v = x[i];
    __nv_bfloat16 h = __float2bfloat16(v);
    g_Xh[i] = h;
    g_Xl[i] = __float2bfloat16(v - __bfloat162float(h));
}

// ---------------------------------------------------------------------------
// Precompute U[t][b][:] = x[b,t,:] @ W_input via the shared MMA tile.
// grid (16, 512), 256 threads.
// ---------------------------------------------------------------------------
__global__ void __launch_bounds__(256) precompute_u_mma()
{
    __shared__ __align__(16) __nv_bfloat16 As_h[64][72];
    __shared__ __align__(16) __nv_bfloat16 As_l[64][72];
    __shared__ __align__(16) __nv_bfloat16 Bs[128][72];
    const int t = blockIdx.y, n0 = blockIdx.x * 128, tid = threadIdx.x;
    mma_tile_64x128(g_Xh + (size_t)t * EDIM, g_Xl + (size_t)t * EDIM,
                    (size_t)RSTEPS * EDIM,
                    g_WiTh + (size_t)n0 * EDIM, g_WiTl + (size_t)n0 * EDIM,
                    EDIM, EDIM / 64,
                    g_U + (size_t)t * BATCH * REC + n0, REC,
                    As_h, As_l, Bs, tid);
}

// ---------------------------------------------------------------------------
// Warp-parallel bucket select (proven equivalent to the serial scan: R5 vs R6
// produced bit-identical outputs). Lane t owns buckets [8t, 8t+8); inclusive
// suffix-sum over lanes finds the bucket holding the k-th largest key.
// ---------------------------------------------------------------------------
__device__ __forceinline__ void bucket_select(
    unsigned* hist, unsigned* sh_prefix, unsigned* sh_k, int shift, int tid)
{
    if (tid < 32) {
        unsigned h[8], lsum = 0;
        int base = tid << 3;
        #pragma unroll
        for (int i = 0; i < 8; i++) { h[i] = hist[base + i]; lsum += h[i]; }
        unsigned inc = lsum;
        #pragma unroll
        for (int off = 16; off > 0; off >>= 1) {
            unsigned v = __shfl_down_sync(0xFFFFFFFFu, inc, off);
            if (tid + off < 32) inc += v;
        }
        unsigned k = *sh_k;
        unsigned above = inc - lsum;
        if (inc >= k && above < k) {
            unsigned S = above;
            #pragma unroll
            for (int i = 7; i >= 0; i--) {
                S += h[i];
                if (S >= k) {
                    *sh_k = k - (S - h[i]);
                    *sh_prefix |= ((unsigned)(base + i) << shift);
                    break;
                }
            }
        }
    }
}

// ---------------------------------------------------------------------------
__device__ __forceinline__ void grid_barrier(unsigned target) {
    __syncthreads();
    if (threadIdx.x == 0) {
        __threadfence();
        atomicAdd(&g_bar, 1u);
        while (*(volatile unsigned*)&g_bar < target) { __nanosleep(32); }
        __threadfence();
    }
    __syncthreads();
}

// ---------------------------------------------------------------------------
// Persistent scan. Phase A (all 128 blocks): one 64x128x256 MMA tile into
// K-split partials. Phase B (blocks 0..63): register-resident gather + fused
// first-pass histogram + warp-scan radix select + tanh + L2-normalize.
// ---------------------------------------------------------------------------
__global__ void __launch_bounds__(PTHREADS) persist_kernel(float* __restrict__ out)
{
    __shared__ __align__(16) __nv_bfloat16 As_h[64][72];
    __shared__ __align__(16) __nv_bfloat16 As_l[64][72];
    __shared__ __align__(16) __nv_bfloat16 Bs[128][72];
    __shared__ unsigned hist[256];
    __shared__ unsigned sh_prefix, sh_k;
    __shared__ float red[8];

    const int bid = blockIdx.x;
    const int tid = threadIdx.x;

    for (int i = bid * PTHREADS + tid; i < BATCH * REC; i += GRID * PTHREADS) {
        g_Rh[i] = __float2bfloat16(0.0f);
        g_Rl[i] = __float2bfloat16(0.0f);
    }
    unsigned baridx = 1;
    grid_barrier(baridx * GRID);

    const int ntile = bid & 15;
    const int kc    = bid >> 4;
    const int n0    = ntile * 128;
    const int kbase = kc * 256;
    const int m     = bid;

    for (int step = 0; step < RSTEPS; step++) {
        // ================= phase A =================
        mma_tile_64x128(g_Rh + kbase, g_Rl + kbase, REC,
                        g_WhT + (size_t)n0 * REC + kbase,
                        g_WlT + (size_t)n0 * REC + kbase,
                        REC, 4,
                        g_part + (size_t)kc * BATCH * REC + n0, REC,
                        As_h, As_l, Bs, tid);
        baridx++;
        grid_barrier(baridx * GRID);

        // ================= phase B =================
        if (bid < BATCH) {
            float zv[8], uv[8];
            hist[tid] = 0u;
            if (tid == 0) { sh_prefix = 0u; sh_k = KTOP; }
            __syncthreads();
            // gather + fused first-pass histogram (shift 24, empty prefix)
            #pragma unroll
            for (int jj = 0; jj < 8; jj++) {
                int j = tid + (jj << 8);
                float zz = 0.0f;
                #pragma unroll
                for (int c = 0; c < 8; c++)
                    zz += g_part[((size_t)c * BATCH + m) * REC + j];
                zv[jj] = zz;
                uv[jj] = g_U[((size_t)step * BATCH + m) * REC + j];
                atomicAdd(&hist[keyOf(zz) >> 24], 1u);
            }
            __syncthreads();
            bucket_select(hist, &sh_prefix, &sh_k, 24, tid);
            __syncthreads();
            // remaining 3 passes from registers
            #pragma unroll
            for (int pi = 0; pi < 3; pi++) {
                const int shift = 16 - (pi << 3);
                hist[tid] = 0u;
                __syncthreads();
                unsigned prefix = sh_prefix;
                unsigned maskH  = 0xFFFFFFFFu << (shift + 8);
                #pragma unroll
                for (int jj = 0; jj < 8; jj++) {
                    unsigned key = keyOf(zv[jj]);
                    if (((key ^ prefix) & maskH) == 0u)
                        atomicAdd(&hist[(key >> shift) & 0xFFu], 1u);
                }
                __syncthreads();
                bucket_select(hist, &sh_prefix, &sh_k, shift, tid);
                __syncthreads();
            }
            const unsigned thKey = sh_prefix;

            float part = 0.0f;
            #pragma unroll
            for (int jj = 0; jj < 8; jj++) {
                float zz = zv[jj];
                float sv = (keyOf(zz) >= thKey) ? zz : 0.0f;
                float v  = tanhf(uv[jj] + sv);
                zv[jj]   = v;
                part += v * v;
            }
            #pragma unroll
            for (int o = 16; o > 0; o >>= 1)
                part += __shfl_down_sync(0xFFFFFFFFu, part, o);
            if ((tid & 31) == 0) red[tid >> 5] = part;
            __syncthreads();
            if (tid < 32) {
                float v = (tid < 8) ? red[tid] : 0.0f;
                #pragma unroll
                for (int o = 4; o > 0; o >>= 1)
                    v += __shfl_down_sync(0xFFFFFFFFu, v, o);
                if (tid == 0) red[0] = v;
            }
            __syncthreads();
            const float inv = 1.0f / (sqrtf(red[0]) + 1e-6f);
            #pragma unroll
            for (int jj = 0; jj < 8; jj++) {
                int j = tid + (jj << 8);
                float v = zv[jj] * inv;
                __nv_bfloat16 h = __float2bfloat16(v);
                g_Rh[(size_t)m * REC + j] = h;
                g_Rl[(size_t)m * REC + j] =
                    __float2bfloat16(v - __bfloat162float(h));
                if (step == RSTEPS - 1) out[(size_t)m * REC + j] = v;
            }
        }
        baridx++;
        if (step < RSTEPS - 1) {
            grid_barrier(baridx * GRID);
        } else {
            __syncthreads();
            if (tid == 0) {
                __threadfence();
                unsigned p = atomicAdd(&g_bar, 1u);
                if (p == (unsigned)NBAR * GRID - 1u) atomicExch(&g_bar, 0u);
            }
        }
    }
}

// ---------------------------------------------------------------------------
extern "C" void kernel_launch(void* const* d_in, const int* in_sizes, int n_in,
                              void* d_out, int out_size)
{
    const float* x  = nullptr;   // 64*512*512  = 16777216
    const float* Wi = nullptr;   // 512*2048    = 1048576
    const float* Wr = nullptr;   // 2048*2048   = 4194304
    for (int i = 0; i < n_in; i++) {
        if      (in_sizes[i] == BATCH * RSTEPS * EDIM) x  = (const float*)d_in[i];
        else if (in_sizes[i] == EDIM * REC)            Wi = (const float*)d_in[i];
        else if (in_sizes[i] == REC * REC)             Wr = (const float*)d_in[i];
    }
    float* out = (float*)d_out;

    split_transpose_kernel<<<dim3(REC / 64, REC / 64), 256>>>(Wr, REC, REC, 0);
    split_transpose_kernel<<<dim3(REC / 64, EDIM / 64), 256>>>(Wi, EDIM, REC, 1);
    split_x_kernel<<<(BATCH * RSTEPS * EDIM) / 256, 256>>>(x);
    precompute_u_mma<<<dim3(REC / 128, RSTEPS), 256>>>();
    persist_kernel<<<GRID, PTHREADS>>>(out);
}

// round 10
// speedup vs baseline: 7.1117x; 1.1306x over previous
#include <cuda_runtime.h>
#include <cuda_bf16.h>

#define REC      2048
#define BATCH    64
#define RSTEPS   512
#define EDIM     512
#define KTOP     819
#define GRID     128
#define PTHREADS 256
#define NBAR     (1 + 2*RSTEPS)

// ---- static device scratch ----
__device__ __nv_bfloat16 g_Rh[BATCH * REC];
__device__ __nv_bfloat16 g_Rl[BATCH * REC];
__device__ __nv_bfloat16 g_WhT[(size_t)REC * REC];        // Wr hi, [n][k]
__device__ __nv_bfloat16 g_WlT[(size_t)REC * REC];        // Wr lo, [n][k] (unused by persist)
__device__ __nv_bfloat16 g_WiTh[(size_t)REC * EDIM];      // Wi hi, [n][k]
__device__ __nv_bfloat16 g_WiTl[(size_t)REC * EDIM];      // Wi lo, [n][k]
__device__ __nv_bfloat16 g_Xh[(size_t)BATCH * RSTEPS * EDIM];
__device__ __nv_bfloat16 g_Xl[(size_t)BATCH * RSTEPS * EDIM];
__device__ float g_part[8 * BATCH * REC];
__device__ float g_U[(size_t)RSTEPS * BATCH * REC];
__device__ unsigned g_bar;

__device__ __forceinline__ unsigned keyOf(float f) {
    unsigned b = __float_as_uint(f);
    return (b & 0x80000000u) ? ~b : (b | 0x80000000u);
}

// ---- tensor-core primitives (R8/R9-proven) ----
__device__ __forceinline__ void ldsm4v(unsigned* r, unsigned addr) {
    asm volatile("ldmatrix.sync.aligned.m8n8.x4.shared.b16 {%0,%1,%2,%3}, [%4];"
                 : "=r"(r[0]), "=r"(r[1]), "=r"(r[2]), "=r"(r[3]) : "r"(addr));
}
__device__ __forceinline__ void mma16816(float* d, const unsigned* a,
                                         unsigned b0, unsigned b1) {
    asm volatile("mma.sync.aligned.m16n8k16.row.col.f32.bf16.bf16.f32 "
                 "{%0,%1,%2,%3}, {%4,%5,%6,%7}, {%8,%9}, {%0,%1,%2,%3};"
                 : "+f"(d[0]), "+f"(d[1]), "+f"(d[2]), "+f"(d[3])
                 : "r"(a[0]), "r"(a[1]), "r"(a[2]), "r"(a[3]), "r"(b0), "r"(b1));
}

// ---------------------------------------------------------------------------
// 64(M) x 128(N) x (nsub*64)(K) tile.
// THREE=true : out = Ah@Bh + Al@Bh + Ah@Bl   (precompute; max precision)
// THREE=false: out = Ah@Bh + Al@Bh           (persist; Bl never touched)
// Fragment math byte-identical to the R8/R9-proven body.
// ---------------------------------------------------------------------------
template <bool THREE>
__device__ __forceinline__ void mma_tile_64x128(
    const __nv_bfloat16* __restrict__ Ah, const __nv_bfloat16* __restrict__ Al,
    size_t strideA,
    const __nv_bfloat16* __restrict__ Bh, const __nv_bfloat16* __restrict__ Bl,
    size_t strideB,
    int nsub,
    float* __restrict__ outBase, size_t strideO,
    __nv_bfloat16 (*As_h)[72], __nv_bfloat16 (*As_l)[72], __nv_bfloat16 (*Bs)[72],
    int tid)
{
    const int lane = tid & 31, wid = tid >> 5;
    const int m0w = (wid & 3) << 4;
    const int n0w = (wid >> 2) << 6;
    const unsigned sAh = (unsigned)__cvta_generic_to_shared(&As_h[0][0]);
    const unsigned sAl = (unsigned)__cvta_generic_to_shared(&As_l[0][0]);
    const unsigned sB  = (unsigned)__cvta_generic_to_shared(&Bs[0][0]);
    const unsigned lrow = (lane & 15);
    const unsigned lcol = (lane >> 4) << 3;

    float acc[8][4];
    #pragma unroll
    for (int f = 0; f < 8; f++)
        #pragma unroll
        for (int q = 0; q < 4; q++) acc[f][q] = 0.0f;

    #pragma unroll 1
    for (int s = 0; s < nsub; s++) {
        const int ksub = s << 6;
        __syncthreads();
        #pragma unroll
        for (int i = 0; i < 2; i++) {
            int c = tid + (i << 8);
            int row = c >> 3, col = (c & 7) << 3;
            *(uint4*)&As_h[row][col] = *(const uint4*)&Ah[(size_t)row * strideA + ksub + col];
            *(uint4*)&As_l[row][col] = *(const uint4*)&Al[(size_t)row * strideA + ksub + col];
        }
        #pragma unroll
        for (int i = 0; i < 4; i++) {
            int c = tid + (i << 8);
            int row = c >> 3, col = (c & 7) << 3;
            *(uint4*)&Bs[row][col] = *(const uint4*)&Bh[(size_t)row * strideB + ksub + col];
        }
        __syncthreads();

        unsigned Afh[4][4], Afl[4][4];
        #pragma unroll
        for (int kst = 0; kst < 4; kst++) {
            unsigned off = ((m0w + lrow) * 72 + (kst << 4) + lcol) << 1;
            ldsm4v(Afh[kst], sAh + off);
            ldsm4v(Afl[kst], sAl + off);
        }
        #pragma unroll
        for (int kst = 0; kst < 4; kst++) {
            #pragma unroll
            for (int ng = 0; ng < 4; ng++) {
                unsigned r[4];
                unsigned off = ((n0w + (ng << 4) + lrow) * 72 + (kst << 4) + lcol) << 1;
                ldsm4v(r, sB + off);
                mma16816(acc[2*ng],   Afh[kst], r[0], r[2]);
                mma16816(acc[2*ng+1], Afh[kst], r[1], r[3]);
                mma16816(acc[2*ng],   Afl[kst], r[0], r[2]);
                mma16816(acc[2*ng+1], Afl[kst], r[1], r[3]);
            }
        }
        if (THREE) {
            __syncthreads();
            #pragma unroll
            for (int i = 0; i < 4; i++) {
                int c = tid + (i << 8);
                int row = c >> 3, col = (c & 7) << 3;
                *(uint4*)&Bs[row][col] = *(const uint4*)&Bl[(size_t)row * strideB + ksub + col];
            }
            __syncthreads();
            #pragma unroll
            for (int kst = 0; kst < 4; kst++) {
                #pragma unroll
                for (int ng = 0; ng < 4; ng++) {
                    unsigned r[4];
                    unsigned off = ((n0w + (ng << 4) + lrow) * 72 + (kst << 4) + lcol) << 1;
                    ldsm4v(r, sB + off);
                    mma16816(acc[2*ng],   Afh[kst], r[0], r[2]);
                    mma16816(acc[2*ng+1], Afh[kst], r[1], r[3]);
                }
            }
        }
    }

    const int g  = lane >> 2;
    const int tg = lane & 3;
    #pragma unroll
    for (int f = 0; f < 8; f++) {
        int coloff = n0w + (f << 3) + (tg << 1);
        int row0   = m0w + g;
        *(float2*)&outBase[(size_t)row0 * strideO + coloff] =
            make_float2(acc[f][0], acc[f][1]);
        *(float2*)&outBase[(size_t)(row0 + 8) * strideO + coloff] =
            make_float2(acc[f][2], acc[f][3]);
    }
}

// ---------------------------------------------------------------------------
// One-time splits.
// ---------------------------------------------------------------------------
__global__ void __launch_bounds__(256) split_transpose_kernel(
    const float* __restrict__ W, int Kdim, int Ndim, int mode)
{
    __shared__ float tile[64][65];
    __nv_bfloat16* outH = mode ? g_WiTh : g_WhT;
    __nv_bfloat16* outL = mode ? g_WiTl : g_WlT;
    const int k0 = blockIdx.y * 64, n0 = blockIdx.x * 64;
    const int tid = threadIdx.x;
    #pragma unroll
    for (int i = 0; i < 16; i++) {
        int idx = tid + (i << 8);
        int r = idx >> 6, c = idx & 63;
        tile[r][c] = W[(size_t)(k0 + r) * Ndim + n0 + c];
    }
    __syncthreads();
    #pragma unroll
    for (int i = 0; i < 16; i++) {
        int idx = tid + (i << 8);
        int nn = idx >> 6, kk = idx & 63;
        float w = tile[kk][nn];
        __nv_bfloat16 h = __float2bfloat16(w);
        outH[(size_t)(n0 + nn) * Kdim + (k0 + kk)] = h;
        outL[(size_t)(n0 + nn) * Kdim + (k0 + kk)] =
            __float2bfloat16(w - __bfloat162float(h));
    }
}

__global__ void __launch_bounds__(256) split_x_kernel(const float* __restrict__ x)
{
    size_t i = (size_t)blockIdx.x * 256 + threadIdx.x;
    float v = x[i];
    __nv_bfloat16 h = __float2bfloat16(v);
    g_Xh[i] = h;
    g_Xl[i] = __float2bfloat16(v - __bfloat162float(h));
}

// ---------------------------------------------------------------------------
// Precompute U = x @ W_input (3-term for precision). grid (16, 512).
// ---------------------------------------------------------------------------
__global__ void __launch_bounds__(256) precompute_u_mma()
{
    __shared__ __align__(16) __nv_bfloat16 As_h[64][72];
    __shared__ __align__(16) __nv_bfloat16 As_l[64][72];
    __shared__ __align__(16) __nv_bfloat16 Bs[128][72];
    const int t = blockIdx.y, n0 = blockIdx.x * 128, tid = threadIdx.x;
    mma_tile_64x128<true>(g_Xh + (size_t)t * EDIM, g_Xl + (size_t)t * EDIM,
                          (size_t)RSTEPS * EDIM,
                          g_WiTh + (size_t)n0 * EDIM, g_WiTl + (size_t)n0 * EDIM,
                          EDIM, EDIM / 64,
                          g_U + (size_t)t * BATCH * REC + n0, REC,
                          As_h, As_l, Bs, tid);
}

// ---------------------------------------------------------------------------
// Warp-parallel bucket select (proven equivalent to serial scan).
// ---------------------------------------------------------------------------
__device__ __forceinline__ void bucket_select(
    unsigned* hist, unsigned* sh_prefix, unsigned* sh_k, int shift, int tid)
{
    if (tid < 32) {
        unsigned h[8], lsum = 0;
        int base = tid << 3;
        #pragma unroll
        for (int i = 0; i < 8; i++) { h[i] = hist[base + i]; lsum += h[i]; }
        unsigned inc = lsum;
        #pragma unroll
        for (int off = 16; off > 0; off >>= 1) {
            unsigned v = __shfl_down_sync(0xFFFFFFFFu, inc, off);
            if (tid + off < 32) inc += v;
        }
        unsigned k = *sh_k;
        unsigned above = inc - lsum;
        if (inc >= k && above < k) {
            unsigned S = above;
            #pragma unroll
            for (int i = 7; i >= 0; i--) {
                S += h[i];
                if (S >= k) {
                    *sh_k = k - (S - h[i]);
                    *sh_prefix |= ((unsigned)(base + i) << shift);
                    break;
                }
            }
        }
    }
}

// ---------------------------------------------------------------------------
__device__ __forceinline__ void grid_barrier(unsigned target) {
    __syncthreads();
    if (threadIdx.x == 0) {
        __threadfence();
        atomicAdd(&g_bar, 1u);
        while (*(volatile unsigned*)&g_bar < target) { }   // tight L2 poll
        __threadfence();
    }
    __syncthreads();
}

// ---------------------------------------------------------------------------
// Persistent scan. Phase A: 2-term MMA tile (z = rh@Wh + rl@Wh).
// Phase B: register-resident gather + radix select + tanh + L2-normalize.
// ---------------------------------------------------------------------------
__global__ void __launch_bounds__(PTHREADS) persist_kernel(float* __restrict__ out)
{
    __shared__ __align__(16) __nv_bfloat16 As_h[64][72];
    __shared__ __align__(16) __nv_bfloat16 As_l[64][72];
    __shared__ __align__(16) __nv_bfloat16 Bs[128][72];
    __shared__ unsigned hist[256];
    __shared__ unsigned sh_prefix, sh_k;
    __shared__ float red[8];

    const int bid = blockIdx.x;
    const int tid = threadIdx.x;

    for (int i = bid * PTHREADS + tid; i < BATCH * REC; i += GRID * PTHREADS) {
        g_Rh[i] = __float2bfloat16(0.0f);
        g_Rl[i] = __float2bfloat16(0.0f);
    }
    unsigned baridx = 1;
    grid_barrier(baridx * GRID);

    const int ntile = bid & 15;
    const int kc    = bid >> 4;
    const int n0    = ntile * 128;
    const int kbase = kc * 256;
    const int m     = bid;

    for (int step = 0; step < RSTEPS; step++) {
        // ================= phase A (2-term) =================
        mma_tile_64x128<false>(g_Rh + kbase, g_Rl + kbase, REC,
                               g_WhT + (size_t)n0 * REC + kbase,
                               (const __nv_bfloat16*)nullptr,
                               REC, 4,
                               g_part + (size_t)kc * BATCH * REC + n0, REC,
                               As_h, As_l, Bs, tid);
        baridx++;
        grid_barrier(baridx * GRID);

        // ================= phase B =================
        if (bid < BATCH) {
            float zv[8], uv[8];
            hist[tid] = 0u;
            if (tid == 0) { sh_prefix = 0u; sh_k = KTOP; }
            __syncthreads();
            #pragma unroll
            for (int jj = 0; jj < 8; jj++) {
                int j = tid + (jj << 8);
                float zz = 0.0f;
                #pragma unroll
                for (int c = 0; c < 8; c++)
                    zz += g_part[((size_t)c * BATCH + m) * REC + j];
                zv[jj] = zz;
                uv[jj] = g_U[((size_t)step * BATCH + m) * REC + j];
                atomicAdd(&hist[keyOf(zz) >> 24], 1u);
            }
            __syncthreads();
            bucket_select(hist, &sh_prefix, &sh_k, 24, tid);
            __syncthreads();
            #pragma unroll
            for (int pi = 0; pi < 3; pi++) {
                const int shift = 16 - (pi << 3);
                hist[tid] = 0u;
                __syncthreads();
                unsigned prefix = sh_prefix;
                unsigned maskH  = 0xFFFFFFFFu << (shift + 8);
                #pragma unroll
                for (int jj = 0; jj < 8; jj++) {
                    unsigned key = keyOf(zv[jj]);
                    if (((key ^ prefix) & maskH) == 0u)
                        atomicAdd(&hist[(key >> shift) & 0xFFu], 1u);
                }
                __syncthreads();
                bucket_select(hist, &sh_prefix, &sh_k, shift, tid);
                __syncthreads();
            }
            const unsigned thKey = sh_prefix;

            float part = 0.0f;
            #pragma unroll
            for (int jj = 0; jj < 8; jj++) {
                float zz = zv[jj];
                float sv = (keyOf(zz) >= thKey) ? zz : 0.0f;
                float v  = tanhf(uv[jj] + sv);
                zv[jj]   = v;
                part += v * v;
            }
            #pragma unroll
            for (int o = 16; o > 0; o >>= 1)
                part += __shfl_down_sync(0xFFFFFFFFu, part, o);
            if ((tid & 31) == 0) red[tid >> 5] = part;
            __syncthreads();
            if (tid < 32) {
                float v = (tid < 8) ? red[tid] : 0.0f;
                #pragma unroll
                for (int o = 4; o > 0; o >>= 1)
                    v += __shfl_down_sync(0xFFFFFFFFu, v, o);
                if (tid == 0) red[0] = v;
            }
            __syncthreads();
            const float inv = 1.0f / (sqrtf(red[0]) + 1e-6f);
            #pragma unroll
            for (int jj = 0; jj < 8; jj++) {
                int j = tid + (jj << 8);
                float v = zv[jj] * inv;
                __nv_bfloat16 h = __float2bfloat16(v);
                g_Rh[(size_t)m * REC + j] = h;
                g_Rl[(size_t)m * REC + j] =
                    __float2bfloat16(v - __bfloat162float(h));
                if (step == RSTEPS - 1) out[(size_t)m * REC + j] = v;
            }
        }
        baridx++;
        if (step < RSTEPS - 1) {
            grid_barrier(baridx * GRID);
        } else {
            __syncthreads();
            if (tid == 0) {
                __threadfence();
                unsigned p = atomicAdd(&g_bar, 1u);
                if (p == (unsigned)NBAR * GRID - 1u) atomicExch(&g_bar, 0u);
            }
        }
    }
}

// ---------------------------------------------------------------------------
extern "C" void kernel_launch(void* const* d_in, const int* in_sizes, int n_in,
                              void* d_out, int out_size)
{
    const float* x  = nullptr;   // 64*512*512  = 16777216
    const float* Wi = nullptr;   // 512*2048    = 1048576
    const float* Wr = nullptr;   // 2048*2048   = 4194304
    for (int i = 0; i < n_in; i++) {
        if      (in_sizes[i] == BATCH * RSTEPS * EDIM) x  = (const float*)d_in[i];
        else if (in_sizes[i] == EDIM * REC)            Wi = (const float*)d_in[i];
        else if (in_sizes[i] == REC * REC)             Wr = (const float*)d_in[i];
    }
    float* out = (float*)d_out;

    split_transpose_kernel<<<dim3(REC / 64, REC / 64), 256>>>(Wr, REC, REC, 0);
    split_transpose_kernel<<<dim3(REC / 64, EDIM / 64), 256>>>(Wi, EDIM, REC, 1);
    split_x_kernel<<<(BATCH * RSTEPS * EDIM) / 256, 256>>>(x);
    precompute_u_mma<<<dim3(REC / 128, RSTEPS), 256>>>();
    persist_kernel<<<GRID, PTHREADS>>>(out);
}

// round 11
// speedup vs baseline: 8.1329x; 1.1436x over previous
#include <cuda_runtime.h>
#include <cuda_bf16.h>

#define REC      2048
#define BATCH    64
#define RSTEPS   512
#define EDIM     512
#define KTOP     819
#define GRID     128
#define PTHREADS 256
#define NBAR     (1 + 2*RSTEPS)

// ---- static device scratch ----
__device__ __nv_bfloat16 g_Rh[BATCH * REC];
__device__ __nv_bfloat16 g_Rl[BATCH * REC];
__device__ __nv_bfloat16 g_WhT[(size_t)REC * REC];        // Wr hi, [n][k]
__device__ __nv_bfloat16 g_WlT[(size_t)REC * REC];        // Wr lo, [n][k]
__device__ __nv_bfloat16 g_WiTh[(size_t)REC * EDIM];      // Wi hi, [n][k]
__device__ __nv_bfloat16 g_WiTl[(size_t)REC * EDIM];      // Wi lo, [n][k]
__device__ __nv_bfloat16 g_Xh[(size_t)BATCH * RSTEPS * EDIM];
__device__ __nv_bfloat16 g_Xl[(size_t)BATCH * RSTEPS * EDIM];
__device__ float g_part[8 * BATCH * REC];
__device__ float g_U[(size_t)RSTEPS * BATCH * REC];
__device__ unsigned g_bar;

__device__ __forceinline__ unsigned keyOf(float f) {
    unsigned b = __float_as_uint(f);
    return (b & 0x80000000u) ? ~b : (b | 0x80000000u);
}
// fast tanh: correct saturation at +/-inf via MUFU exp/rcp
__device__ __forceinline__ float ftanh(float x) {
    float t = __expf(2.0f * x);
    return 1.0f - __fdividef(2.0f, t + 1.0f);
}

// ---- tensor-core primitives (R8/R9-proven) ----
__device__ __forceinline__ void ldsm4v(unsigned* r, unsigned addr) {
    asm volatile("ldmatrix.sync.aligned.m8n8.x4.shared.b16 {%0,%1,%2,%3}, [%4];"
                 : "=r"(r[0]), "=r"(r[1]), "=r"(r[2]), "=r"(r[3]) : "r"(addr));
}
__device__ __forceinline__ void mma16816(float* d, const unsigned* a,
                                         unsigned b0, unsigned b1) {
    asm volatile("mma.sync.aligned.m16n8k16.row.col.f32.bf16.bf16.f32 "
                 "{%0,%1,%2,%3}, {%4,%5,%6,%7}, {%8,%9}, {%0,%1,%2,%3};"
                 : "+f"(d[0]), "+f"(d[1]), "+f"(d[2]), "+f"(d[3])
                 : "r"(a[0]), "r"(a[1]), "r"(a[2]), "r"(a[3]), "r"(b0), "r"(b1));
}

// ---------------------------------------------------------------------------
// 64(M) x 128(N) x (nsub*64)(K) tile with REGISTER PREFETCH (loads for
// ksub+1 issued before the MMA block of ksub; fragment math unchanged).
// THREE=true : out = Ah@Bh + Al@Bh + Ah@Bl ; THREE=false: out = Ah@Bh + Al@Bh
// ---------------------------------------------------------------------------
template <bool THREE>
__device__ __forceinline__ void mma_tile_64x128(
    const __nv_bfloat16* __restrict__ Ah, const __nv_bfloat16* __restrict__ Al,
    size_t strideA,
    const __nv_bfloat16* __restrict__ Bh, const __nv_bfloat16* __restrict__ Bl,
    size_t strideB,
    int nsub,
    float* __restrict__ outBase, size_t strideO,
    __nv_bfloat16 (*As_h)[72], __nv_bfloat16 (*As_l)[72], __nv_bfloat16 (*Bs)[72],
    int tid)
{
    const int lane = tid & 31, wid = tid >> 5;
    const int m0w = (wid & 3) << 4;
    const int n0w = (wid >> 2) << 6;
    const unsigned sAh = (unsigned)__cvta_generic_to_shared(&As_h[0][0]);
    const unsigned sAl = (unsigned)__cvta_generic_to_shared(&As_l[0][0]);
    const unsigned sB  = (unsigned)__cvta_generic_to_shared(&Bs[0][0]);
    const unsigned lrow = (lane & 15);
    const unsigned lcol = (lane >> 4) << 3;

    // loader decomposition (same as R10)
    const int ar0 = tid >> 3,         ac0 = (tid & 7) << 3;          // A row/col
    const int ar1 = (tid + 256) >> 3;                                 // A row, i=1
    const int br0 = tid >> 3;                                         // B rows i=0..3
    float acc[8][4];
    #pragma unroll
    for (int f = 0; f < 8; f++)
        #pragma unroll
        for (int q = 0; q < 4; q++) acc[f][q] = 0.0f;

    uint4 pAh[2], pAl[2], pBh[4], pBl[4];
    // prefetch ksub = 0
    pAh[0] = *(const uint4*)&Ah[(size_t)ar0 * strideA + ac0];
    pAl[0] = *(const uint4*)&Al[(size_t)ar0 * strideA + ac0];
    pAh[1] = *(const uint4*)&Ah[(size_t)ar1 * strideA + ac0];
    pAl[1] = *(const uint4*)&Al[(size_t)ar1 * strideA + ac0];
    #pragma unroll
    for (int i = 0; i < 4; i++) {
        pBh[i] = *(const uint4*)&Bh[(size_t)(br0 + (i << 5)) * strideB + ac0];
        if (THREE)
            pBl[i] = *(const uint4*)&Bl[(size_t)(br0 + (i << 5)) * strideB + ac0];
    }

    #pragma unroll 1
    for (int s = 0; s < nsub; s++) {
        __syncthreads();                     // prior iter's ldsm complete
        *(uint4*)&As_h[ar0][ac0] = pAh[0];
        *(uint4*)&As_l[ar0][ac0] = pAl[0];
        *(uint4*)&As_h[ar1][ac0] = pAh[1];
        *(uint4*)&As_l[ar1][ac0] = pAl[1];
        #pragma unroll
        for (int i = 0; i < 4; i++)
            *(uint4*)&Bs[br0 + (i << 5)][ac0] = pBh[i];
        __syncthreads();

        // prefetch ksub = s+1 (overlaps with MMA below)
        if (s + 1 < nsub) {
            const int kn = (s + 1) << 6;
            pAh[0] = *(const uint4*)&Ah[(size_t)ar0 * strideA + kn + ac0];
            pAl[0] = *(const uint4*)&Al[(size_t)ar0 * strideA + kn + ac0];
            pAh[1] = *(const uint4*)&Ah[(size_t)ar1 * strideA + kn + ac0];
            pAl[1] = *(const uint4*)&Al[(size_t)ar1 * strideA + kn + ac0];
            #pragma unroll
            for (int i = 0; i < 4; i++)
                pBh[i] = *(const uint4*)&Bh[(size_t)(br0 + (i << 5)) * strideB + kn + ac0];
        }

        unsigned Afh[4][4], Afl[4][4];
        #pragma unroll
        for (int kst = 0; kst < 4; kst++) {
            unsigned off = ((m0w + lrow) * 72 + (kst << 4) + lcol) << 1;
            ldsm4v(Afh[kst], sAh + off);
            ldsm4v(Afl[kst], sAl + off);
        }
        #pragma unroll
        for (int kst = 0; kst < 4; kst++) {
            #pragma unroll
            for (int ng = 0; ng < 4; ng++) {
                unsigned r[4];
                unsigned off = ((n0w + (ng << 4) + lrow) * 72 + (kst << 4) + lcol) << 1;
                ldsm4v(r, sB + off);
                mma16816(acc[2*ng],   Afh[kst], r[0], r[2]);
                mma16816(acc[2*ng+1], Afh[kst], r[1], r[3]);
                mma16816(acc[2*ng],   Afl[kst], r[0], r[2]);
                mma16816(acc[2*ng+1], Afl[kst], r[1], r[3]);
            }
        }
        if (THREE) {
            __syncthreads();
            #pragma unroll
            for (int i = 0; i < 4; i++)
                *(uint4*)&Bs[br0 + (i << 5)][ac0] = pBl[i];
            __syncthreads();
            // prefetch next Bl AFTER current pBl consumed
            if (s + 1 < nsub) {
                const int kn = (s + 1) << 6;
                #pragma unroll
                for (int i = 0; i < 4; i++)
                    pBl[i] = *(const uint4*)&Bl[(size_t)(br0 + (i << 5)) * strideB + kn + ac0];
            }
            #pragma unroll
            for (int kst = 0; kst < 4; kst++) {
                #pragma unroll
                for (int ng = 0; ng < 4; ng++) {
                    unsigned r[4];
                    unsigned off = ((n0w + (ng << 4) + lrow) * 72 + (kst << 4) + lcol) << 1;
                    ldsm4v(r, sB + off);
                    mma16816(acc[2*ng],   Afh[kst], r[0], r[2]);
                    mma16816(acc[2*ng+1], Afh[kst], r[1], r[3]);
                }
            }
        }
    }

    const int g  = lane >> 2;
    const int tg = lane & 3;
    #pragma unroll
    for (int f = 0; f < 8; f++) {
        int coloff = n0w + (f << 3) + (tg << 1);
        int row0   = m0w + g;
        *(float2*)&outBase[(size_t)row0 * strideO + coloff] =
            make_float2(acc[f][0], acc[f][1]);
        *(float2*)&outBase[(size_t)(row0 + 8) * strideO + coloff] =
            make_float2(acc[f][2], acc[f][3]);
    }
}

// ---------------------------------------------------------------------------
// One-time splits.
// ---------------------------------------------------------------------------
__global__ void __launch_bounds__(256) split_transpose_kernel(
    const float* __restrict__ W, int Kdim, int Ndim, int mode)
{
    __shared__ float tile[64][65];
    __nv_bfloat16* outH = mode ? g_WiTh : g_WhT;
    __nv_bfloat16* outL = mode ? g_WiTl : g_WlT;
    const int k0 = blockIdx.y * 64, n0 = blockIdx.x * 64;
    const int tid = threadIdx.x;
    #pragma unroll
    for (int i = 0; i < 16; i++) {
        int idx = tid + (i << 8);
        int r = idx >> 6, c = idx & 63;
        tile[r][c] = W[(size_t)(k0 + r) * Ndim + n0 + c];
    }
    __syncthreads();
    #pragma unroll
    for (int i = 0; i < 16; i++) {
        int idx = tid + (i << 8);
        int nn = idx >> 6, kk = idx & 63;
        float w = tile[kk][nn];
        __nv_bfloat16 h = __float2bfloat16(w);
        outH[(size_t)(n0 + nn) * Kdim + (k0 + kk)] = h;
        outL[(size_t)(n0 + nn) * Kdim + (k0 + kk)] =
            __float2bfloat16(w - __bfloat162float(h));
    }
}

__global__ void __launch_bounds__(256) split_x_kernel(const float* __restrict__ x)
{
    size_t i = (size_t)blockIdx.x * 256 + threadIdx.x;
    float v = x[i];
    __nv_bfloat16 h = __float2bfloat16(v);
    g_Xh[i] = h;
    g_Xl[i] = __float2bfloat16(v - __bfloat162float(h));
}

// ---------------------------------------------------------------------------
// Precompute U = x @ W_input (3-term). grid (16, 512).
// ---------------------------------------------------------------------------
__global__ void __launch_bounds__(256) precompute_u_mma()
{
    __shared__ __align__(16) __nv_bfloat16 As_h[64][72];
    __shared__ __align__(16) __nv_bfloat16 As_l[64][72];
    __shared__ __align__(16) __nv_bfloat16 Bs[128][72];
    const int t = blockIdx.y, n0 = blockIdx.x * 128, tid = threadIdx.x;
    mma_tile_64x128<true>(g_Xh + (size_t)t * EDIM, g_Xl + (size_t)t * EDIM,
                          (size_t)RSTEPS * EDIM,
                          g_WiTh + (size_t)n0 * EDIM, g_WiTl + (size_t)n0 * EDIM,
                          EDIM, EDIM / 64,
                          g_U + (size_t)t * BATCH * REC + n0, REC,
                          As_h, As_l, Bs, tid);
}

// ---------------------------------------------------------------------------
// Warp-parallel bucket select (proven equivalent to serial scan).
// ---------------------------------------------------------------------------
__device__ __forceinline__ void bucket_select(
    unsigned* hist, unsigned* sh_prefix, unsigned* sh_k, int shift, int tid)
{
    if (tid < 32) {
        unsigned h[8], lsum = 0;
        int base = tid << 3;
        #pragma unroll
        for (int i = 0; i < 8; i++) { h[i] = hist[base + i]; lsum += h[i]; }
        unsigned inc = lsum;
        #pragma unroll
        for (int off = 16; off > 0; off >>= 1) {
            unsigned v = __shfl_down_sync(0xFFFFFFFFu, inc, off);
            if (tid + off < 32) inc += v;
        }
        unsigned k = *sh_k;
        unsigned above = inc - lsum;
        if (inc >= k && above < k) {
            unsigned S = above;
            #pragma unroll
            for (int i = 7; i >= 0; i--) {
                S += h[i];
                if (S >= k) {
                    *sh_k = k - (S - h[i]);
                    *sh_prefix |= ((unsigned)(base + i) << shift);
                    break;
                }
            }
        }
    }
}

// ---------------------------------------------------------------------------
__device__ __forceinline__ void grid_barrier(unsigned target) {
    __syncthreads();
    if (threadIdx.x == 0) {
        __threadfence();
        atomicAdd(&g_bar, 1u);
        while (*(volatile unsigned*)&g_bar < target) { }
        __threadfence();
    }
    __syncthreads();
}

// ---------------------------------------------------------------------------
// Persistent scan. Phase A: 2-term MMA tile. Phase B: float4-vectorized
// gather + warp-scan radix select + fast tanh + L2-normalize.
// j mapping (phase B): thread tid owns j = 4*tid + e + 1024*g, e<4, g<2.
// ---------------------------------------------------------------------------
__global__ void __launch_bounds__(PTHREADS) persist_kernel(float* __restrict__ out)
{
    __shared__ __align__(16) __nv_bfloat16 As_h[64][72];
    __shared__ __align__(16) __nv_bfloat16 As_l[64][72];
    __shared__ __align__(16) __nv_bfloat16 Bs[128][72];
    __shared__ unsigned hist[256];
    __shared__ unsigned sh_prefix, sh_k;
    __shared__ float red[8];

    const int bid = blockIdx.x;
    const int tid = threadIdx.x;

    for (int i = bid * PTHREADS + tid; i < BATCH * REC; i += GRID * PTHREADS) {
        g_Rh[i] = __float2bfloat16(0.0f);
        g_Rl[i] = __float2bfloat16(0.0f);
    }
    unsigned baridx = 1;
    grid_barrier(baridx * GRID);

    const int ntile = bid & 15;
    const int kc    = bid >> 4;
    const int n0    = ntile * 128;
    const int kbase = kc * 256;
    const int m     = bid;

    for (int step = 0; step < RSTEPS; step++) {
        // ================= phase A (2-term) =================
        mma_tile_64x128<false>(g_Rh + kbase, g_Rl + kbase, REC,
                               g_WhT + (size_t)n0 * REC + kbase,
                               (const __nv_bfloat16*)nullptr,
                               REC, 4,
                               g_part + (size_t)kc * BATCH * REC + n0, REC,
                               As_h, As_l, Bs, tid);
        baridx++;
        grid_barrier(baridx * GRID);

        // ================= phase B =================
        if (bid < BATCH) {
            float zv[8], uv[8];
            hist[tid] = 0u;
            if (tid == 0) { sh_prefix = 0u; sh_k = KTOP; }
            __syncthreads();
            // vectorized gather + fused first-pass histogram
            #pragma unroll
            for (int g2 = 0; g2 < 2; g2++) {
                const int j4 = (tid << 2) + (g2 << 10);
                float4 a = make_float4(0.f, 0.f, 0.f, 0.f);
                #pragma unroll
                for (int c = 0; c < 8; c++) {
                    float4 p = *(const float4*)&g_part[((size_t)c * BATCH + m) * REC + j4];
                    a.x += p.x; a.y += p.y; a.z += p.z; a.w += p.w;
                }
                zv[g2*4+0] = a.x; zv[g2*4+1] = a.y; zv[g2*4+2] = a.z; zv[g2*4+3] = a.w;
                float4 u4 = *(const float4*)&g_U[((size_t)step * BATCH + m) * REC + j4];
                uv[g2*4+0] = u4.x; uv[g2*4+1] = u4.y; uv[g2*4+2] = u4.z; uv[g2*4+3] = u4.w;
                atomicAdd(&hist[keyOf(a.x) >> 24], 1u);
                atomicAdd(&hist[keyOf(a.y) >> 24], 1u);
                atomicAdd(&hist[keyOf(a.z) >> 24], 1u);
                atomicAdd(&hist[keyOf(a.w) >> 24], 1u);
            }
            __syncthreads();
            bucket_select(hist, &sh_prefix, &sh_k, 24, tid);
            __syncthreads();
            #pragma unroll
            for (int pi = 0; pi < 3; pi++) {
                const int shift = 16 - (pi << 3);
                hist[tid] = 0u;
                __syncthreads();
                unsigned prefix = sh_prefix;
                unsigned maskH  = 0xFFFFFFFFu << (shift + 8);
                #pragma unroll
                for (int jj = 0; jj < 8; jj++) {
                    unsigned key = keyOf(zv[jj]);
                    if (((key ^ prefix) & maskH) == 0u)
                        atomicAdd(&hist[(key >> shift) & 0xFFu], 1u);
                }
                __syncthreads();
                bucket_select(hist, &sh_prefix, &sh_k, shift, tid);
                __syncthreads();
            }
            const unsigned thKey = sh_prefix;

            float part = 0.0f;
            #pragma unroll
            for (int jj = 0; jj < 8; jj++) {
                float zz = zv[jj];
                float sv = (keyOf(zz) >= thKey) ? zz : 0.0f;
                float v  = ftanh(uv[jj] + sv);
                zv[jj]   = v;
                part += v * v;
            }
            #pragma unroll
            for (int o = 16; o > 0; o >>= 1)
                part += __shfl_down_sync(0xFFFFFFFFu, part, o);
            if ((tid & 31) == 0) red[tid >> 5] = part;
            __syncthreads();
            if (tid < 32) {
                float v = (tid < 8) ? red[tid] : 0.0f;
                #pragma unroll
                for (int o = 4; o > 0; o >>= 1)
                    v += __shfl_down_sync(0xFFFFFFFFu, v, o);
                if (tid == 0) red[0] = v;
            }
            __syncthreads();
            const float inv = 1.0f / (sqrtf(red[0]) + 1e-6f);
            #pragma unroll
            for (int g2 = 0; g2 < 2; g2++) {
                const int j4 = (tid << 2) + (g2 << 10);
                float v0 = zv[g2*4+0] * inv, v1 = zv[g2*4+1] * inv;
                float v2 = zv[g2*4+2] * inv, v3 = zv[g2*4+3] * inv;
                __nv_bfloat16 h0 = __float2bfloat16(v0), h1 = __float2bfloat16(v1);
                __nv_bfloat16 h2 = __float2bfloat16(v2), h3 = __float2bfloat16(v3);
                __nv_bfloat16 l0 = __float2bfloat16(v0 - __bfloat162float(h0));
                __nv_bfloat16 l1 = __float2bfloat16(v1 - __bfloat162float(h1));
                __nv_bfloat16 l2 = __float2bfloat16(v2 - __bfloat162float(h2));
                __nv_bfloat16 l3 = __float2bfloat16(v3 - __bfloat162float(h3));
                __nv_bfloat162 hp0, hp1, lp0, lp1;
                hp0.x = h0; hp0.y = h1; hp1.x = h2; hp1.y = h3;
                lp0.x = l0; lp0.y = l1; lp1.x = l2; lp1.y = l3;
                *(__nv_bfloat162*)&g_Rh[(size_t)m * REC + j4]     = hp0;
                *(__nv_bfloat162*)&g_Rh[(size_t)m * REC + j4 + 2] = hp1;
                *(__nv_bfloat162*)&g_Rl[(size_t)m * REC + j4]     = lp0;
                *(__nv_bfloat162*)&g_Rl[(size_t)m * REC + j4 + 2] = lp1;
                if (step == RSTEPS - 1)
                    *(float4*)&out[(size_t)m * REC + j4] = make_float4(v0, v1, v2, v3);
            }
        }
        baridx++;
        if (step < RSTEPS - 1) {
            grid_barrier(baridx * GRID);
        } else {
            __syncthreads();
            if (tid == 0) {
                __threadfence();
                unsigned p = atomicAdd(&g_bar, 1u);
                if (p == (unsigned)NBAR * GRID - 1u) atomicExch(&g_bar, 0u);
            }
        }
    }
}

// ---------------------------------------------------------------------------
extern "C" void kernel_launch(void* const* d_in, const int* in_sizes, int n_in,
                              void* d_out, int out_size)
{
    const float* x  = nullptr;   // 64*512*512  = 16777216
    const float* Wi = nullptr;   // 512*2048    = 1048576
    const float* Wr = nullptr;   // 2048*2048   = 4194304
    for (int i = 0; i < n_in; i++) {
        if      (in_sizes[i] == BATCH * RSTEPS * EDIM) x  = (const float*)d_in[i];
        else if (in_sizes[i] == EDIM * REC)            Wi = (const float*)d_in[i];
        else if (in_sizes[i] == REC * REC)             Wr = (const float*)d_in[i];
    }
    float* out = (float*)d_out;

    split_transpose_kernel<<<dim3(REC / 64, REC / 64), 256>>>(Wr, REC, REC, 0);
    split_transpose_kernel<<<dim3(REC / 64, EDIM / 64), 256>>>(Wi, EDIM, REC, 1);
    split_x_kernel<<<(BATCH * RSTEPS * EDIM) / 256, 256>>>(x);
    precompute_u_mma<<<dim3(REC / 128, RSTEPS), 256>>>();
    persist_kernel<<<GRID, PTHREADS>>>(out);
}